// round 1
// baseline (speedup 1.0000x reference)
#include <cuda_runtime.h>
#include <cuda_bf16.h>
#include <math.h>
#include <stdint.h>

// ---------------------------------------------------------------------------
// ParallelSSM: rmsnorm -> proj -> (softplus dt) -> chunked selective scan -> out proj
// Shapes: tokens = B*L = 8192, DIM=1024, STATE=64, DT_RANK=64, CHUNK=64, P=192
// ---------------------------------------------------------------------------

#define DIMD   1024
#define STATE  64
#define DTRANK 64
#define CHUNKT 64
#define PDIM   192          // DT_RANK + 2*STATE
#define MAX_TOKENS 8192

// Scratch (device globals: allocation-free rule)
__device__ float g_xn  [(size_t)MAX_TOKENS * DIMD];   // 32 MB  rmsnormed x
__device__ float g_proj[(size_t)MAX_TOKENS * PDIM];   // 6 MB   [dt_lo | B | C]
__device__ float g_dt  [(size_t)MAX_TOKENS * DIMD];   // 32 MB  softplus delta
__device__ float g_y   [(size_t)MAX_TOKENS * DIMD];   // 32 MB  y + x*D
__device__ float g_A   [(size_t)DIMD * STATE];        // 256 KB -exp(A_log)

// ---------------------------------------------------------------------------
// K0: A = -exp(A_log)
// ---------------------------------------------------------------------------
__global__ void prep_A_kernel(const float* __restrict__ a_log, float* __restrict__ a_out, int n) {
    int i = blockIdx.x * blockDim.x + threadIdx.x;
    if (i < n) a_out[i] = -expf(a_log[i]);
}

// ---------------------------------------------------------------------------
// K1: rmsnorm, one block per token, 256 threads * float4 = 1024 elems
// ---------------------------------------------------------------------------
__global__ __launch_bounds__(256)
void rmsnorm_kernel(const float* __restrict__ x, const float* __restrict__ w,
                    float* __restrict__ o) {
    int tok = blockIdx.x;
    int tid = threadIdx.x;
    size_t base = (size_t)tok * DIMD;
    float4 v = *(const float4*)(x + base + tid * 4);
    float ss = v.x*v.x + v.y*v.y + v.z*v.z + v.w*v.w;
    #pragma unroll
    for (int off = 16; off > 0; off >>= 1)
        ss += __shfl_xor_sync(0xffffffffu, ss, off);
    __shared__ float red[8];
    if ((tid & 31) == 0) red[tid >> 5] = ss;
    __syncthreads();
    float tot = red[0] + red[1] + red[2] + red[3] + red[4] + red[5] + red[6] + red[7];
    float s = rsqrtf(tot * (1.0f / (float)DIMD) + 1e-6f);
    float4 wv = *(const float4*)(w + tid * 4);
    float4 r;
    r.x = v.x * s * wv.x; r.y = v.y * s * wv.y;
    r.z = v.z * s * wv.z; r.w = v.w * s * wv.w;
    *(float4*)(o + base + tid * 4) = r;
}

// ---------------------------------------------------------------------------
// Generic NT GEMM: C[M,N] = A[M,K] * B[N,K]^T (all row-major, K contiguous)
// BM=128 BN=64 BK=16, 256 threads, 8x4 per thread.
// EPI==0: plain store. EPI==1: softplus(acc + bias[n]).
// M, N assumed multiples of BM/BN; K multiple of BK.
// ---------------------------------------------------------------------------
template<int EPI>
__global__ __launch_bounds__(256)
void gemm_nt_kernel(const float* __restrict__ A, int lda,
                    const float* __restrict__ B, int ldb,
                    float* __restrict__ C, int ldc,
                    int K, const float* __restrict__ bias) {
    constexpr int BM = 128, BN = 64, BK = 16, TM = 8, TN = 4;
    __shared__ float As[BK][BM];
    __shared__ float Bs[BK][BN];

    int tid = threadIdx.x;
    int m0 = blockIdx.x * BM;
    int n0 = blockIdx.y * BN;
    int tx = tid & 15;        // n dir
    int ty = tid >> 4;        // m dir
    int row0 = ty * TM;
    int col0 = tx * TN;

    float acc[TM][TN];
    #pragma unroll
    for (int i = 0; i < TM; i++)
        #pragma unroll
        for (int j = 0; j < TN; j++) acc[i][j] = 0.0f;

    for (int k0 = 0; k0 < K; k0 += BK) {
        // load A tile: 128 rows x 16 cols = 512 float4
        #pragma unroll
        for (int q = 0; q < 2; q++) {
            int i = tid + q * 256;
            int r = i >> 2, c4 = i & 3;
            float4 v = *(const float4*)(A + (size_t)(m0 + r) * lda + k0 + c4 * 4);
            As[c4 * 4 + 0][r] = v.x;
            As[c4 * 4 + 1][r] = v.y;
            As[c4 * 4 + 2][r] = v.z;
            As[c4 * 4 + 3][r] = v.w;
        }
        // load B tile: 64 rows x 16 cols = 256 float4
        {
            int r = tid >> 2, c4 = tid & 3;
            float4 v = *(const float4*)(B + (size_t)(n0 + r) * ldb + k0 + c4 * 4);
            Bs[c4 * 4 + 0][r] = v.x;
            Bs[c4 * 4 + 1][r] = v.y;
            Bs[c4 * 4 + 2][r] = v.z;
            Bs[c4 * 4 + 3][r] = v.w;
        }
        __syncthreads();
        #pragma unroll
        for (int kk = 0; kk < BK; kk++) {
            float4 a0 = *(const float4*)&As[kk][row0];
            float4 a1 = *(const float4*)&As[kk][row0 + 4];
            float4 bv = *(const float4*)&Bs[kk][col0];
            float a[TM] = {a0.x, a0.y, a0.z, a0.w, a1.x, a1.y, a1.z, a1.w};
            float b[TN] = {bv.x, bv.y, bv.z, bv.w};
            #pragma unroll
            for (int i = 0; i < TM; i++)
                #pragma unroll
                for (int j = 0; j < TN; j++)
                    acc[i][j] = fmaf(a[i], b[j], acc[i][j]);
        }
        __syncthreads();
    }

    #pragma unroll
    for (int i = 0; i < TM; i++) {
        size_t off = (size_t)(m0 + row0 + i) * ldc + n0 + col0;
        float4 v;
        float t[TN];
        #pragma unroll
        for (int j = 0; j < TN; j++) {
            float a = acc[i][j];
            if (EPI == 1) {
                a += bias[n0 + col0 + j];
                a = fmaxf(a, 0.0f) + log1pf(__expf(-fabsf(a)));
            }
            t[j] = a;
        }
        v.x = t[0]; v.y = t[1]; v.z = t[2]; v.w = t[3];
        *(float4*)(C + off) = v;
    }
}

// ---------------------------------------------------------------------------
// K4: chunked selective scan.
// grid.x = chunks (tokens/64), grid.y = DIM/128. 128 threads, one d each.
// Per thread: h[64] + A[64] in registers. B/C for the whole chunk in shared.
// y_out = sum_n h[n]*C[t,n] + x_orig * D   (residual fused)
// ---------------------------------------------------------------------------
__global__ __launch_bounds__(128, 2)
void scan_kernel(const float* __restrict__ xn, const float* __restrict__ dt,
                 const float* __restrict__ proj, const float* __restrict__ Aarr,
                 const float* __restrict__ xorig, const float* __restrict__ Dvec,
                 float* __restrict__ yout) {
    __shared__ float4 BC[CHUNKT * 32];   // per t: 16 float4 of B then 16 of C (32 KB)

    int chunk = blockIdx.x;
    int dbase = blockIdx.y * 128;
    int tid = threadIdx.x;
    int tok0 = chunk * CHUNKT;
    int d = dbase + tid;

    // stage B|C (proj cols [64:192) are contiguous: 32 float4 per token)
    for (int i = tid; i < CHUNKT * 32; i += 128) {
        int t = i >> 5;
        int j = i & 31;
        BC[t * 32 + j] = *(const float4*)(proj + (size_t)(tok0 + t) * PDIM + DTRANK + j * 4);
    }

    // A row into registers
    float Areg[STATE];
    {
        const float4* Ar = (const float4*)(Aarr + (size_t)d * STATE);
        #pragma unroll
        for (int j = 0; j < 16; j++) {
            float4 v = Ar[j];
            Areg[4 * j + 0] = v.x; Areg[4 * j + 1] = v.y;
            Areg[4 * j + 2] = v.z; Areg[4 * j + 3] = v.w;
        }
    }
    float h[STATE];
    #pragma unroll
    for (int n = 0; n < STATE; n++) h[n] = 0.0f;

    float Dd = Dvec[d];
    __syncthreads();

    size_t base = (size_t)tok0 * DIMD + d;
    float dt_n = dt[base];
    float xn_n = xn[base];
    float xo_n = xorig[base];

    for (int t = 0; t < CHUNKT; t++) {
        float dtc = dt_n, xnc = xn_n, xoc = xo_n;
        if (t < CHUNKT - 1) {
            size_t b2 = base + (size_t)(t + 1) * DIMD;
            dt_n = dt[b2]; xn_n = xn[b2]; xo_n = xorig[b2];
        }
        float dx = dtc * xnc;
        float y = 0.0f;
        const float4* Bt = &BC[t * 32];
        #pragma unroll
        for (int j = 0; j < 16; j++) {
            float4 b4 = Bt[j];
            float4 c4 = Bt[j + 16];
            float e0 = __expf(dtc * Areg[4 * j + 0]);
            float e1 = __expf(dtc * Areg[4 * j + 1]);
            float e2 = __expf(dtc * Areg[4 * j + 2]);
            float e3 = __expf(dtc * Areg[4 * j + 3]);
            h[4 * j + 0] = fmaf(e0, h[4 * j + 0], dx * b4.x);
            h[4 * j + 1] = fmaf(e1, h[4 * j + 1], dx * b4.y);
            h[4 * j + 2] = fmaf(e2, h[4 * j + 2], dx * b4.z);
            h[4 * j + 3] = fmaf(e3, h[4 * j + 3], dx * b4.w);
            y = fmaf(h[4 * j + 0], c4.x, y);
            y = fmaf(h[4 * j + 1], c4.y, y);
            y = fmaf(h[4 * j + 2], c4.z, y);
            y = fmaf(h[4 * j + 3], c4.w, y);
        }
        yout[base + (size_t)t * DIMD] = y + xoc * Dd;
    }
}

// ---------------------------------------------------------------------------
// launch
// ---------------------------------------------------------------------------
extern "C" void kernel_launch(void* const* d_in, const int* in_sizes, int n_in,
                              void* d_out, int out_size) {
    const float* x      = (const float*)d_in[0];   // [B,L,1024]
    const float* norm_w = (const float*)d_in[1];   // [1024]
    const float* xpw    = (const float*)d_in[2];   // [192,1024]
    const float* dtw    = (const float*)d_in[3];   // [1024,64]
    const float* dtb    = (const float*)d_in[4];   // [1024]
    const float* alog   = (const float*)d_in[5];   // [1024,64]
    const float* Dvec   = (const float*)d_in[6];   // [1024]
    const float* ow     = (const float*)d_in[7];   // [1024,1024]
    float* out = (float*)d_out;

    int tokens = in_sizes[0] / DIMD;               // 8192

    float *p_xn, *p_proj, *p_dt, *p_y, *p_A;
    cudaGetSymbolAddress((void**)&p_xn,   g_xn);
    cudaGetSymbolAddress((void**)&p_proj, g_proj);
    cudaGetSymbolAddress((void**)&p_dt,   g_dt);
    cudaGetSymbolAddress((void**)&p_y,    g_y);
    cudaGetSymbolAddress((void**)&p_A,    g_A);

    // K0: A = -exp(A_log)
    prep_A_kernel<<<(DIMD * STATE + 255) / 256, 256>>>(alog, p_A, DIMD * STATE);

    // K1: rmsnorm
    rmsnorm_kernel<<<tokens, 256>>>(x, norm_w, p_xn);

    // K2: proj = xn @ xpw^T   [tokens,192]
    gemm_nt_kernel<0><<<dim3(tokens / 128, PDIM / 64), 256>>>(
        p_xn, DIMD, xpw, DIMD, p_proj, PDIM, DIMD, nullptr);

    // K3: dt = softplus(proj[:, :64] @ dtw^T + dtb)   [tokens,1024]
    gemm_nt_kernel<1><<<dim3(tokens / 128, DIMD / 64), 256>>>(
        p_proj, PDIM, dtw, DTRANK, p_dt, DIMD, DTRANK, dtb);

    // K4: scan -> y + x*D
    scan_kernel<<<dim3(tokens / CHUNKT, DIMD / 128), 128>>>(
        p_xn, p_dt, p_proj, p_A, x, Dvec, p_y);

    // K5: out = y @ ow^T   [tokens,1024]
    gemm_nt_kernel<0><<<dim3(tokens / 128, DIMD / 64), 256>>>(
        p_y, DIMD, ow, DIMD, out, DIMD, DIMD, nullptr);
}

// round 5
// speedup vs baseline: 1.6177x; 1.6177x over previous
#include <cuda_runtime.h>
#include <cuda_bf16.h>
#include <math.h>
#include <stdint.h>

// ---------------------------------------------------------------------------
// ParallelSSM: rmsnorm -> proj -> (softplus dt) -> chunked selective scan -> out proj
// tokens = B*L = 8192, DIM=1024, STATE=64, DT_RANK=64, CHUNK=64, P=192
// K=1024 GEMMs via mma.sync tf32 (base sm_100 target: tcgen05 not assemblable).
// ---------------------------------------------------------------------------

#define DIMD   1024
#define STATE  64
#define DTRANK 64
#define CHUNKT 64
#define PDIM   192
#define MAX_TOKENS 8192

// Scratch (device globals: allocation-free rule)
__device__ float g_xn  [(size_t)MAX_TOKENS * DIMD];
__device__ float g_proj[(size_t)MAX_TOKENS * PDIM];
__device__ float g_dt  [(size_t)MAX_TOKENS * DIMD];
__device__ float g_y   [(size_t)MAX_TOKENS * DIMD];
__device__ float g_A   [(size_t)DIMD * STATE];

// ============================ mma.sync helpers =============================
__device__ __forceinline__ uint32_t f2tf(float x) {
    uint32_t u;
    asm("cvt.rna.tf32.f32 %0, %1;" : "=r"(u) : "f"(x));
    return u;
}

__device__ __forceinline__ void mma_tf32(float c[4], const uint32_t a[4], const uint32_t b[2]) {
    asm volatile(
        "mma.sync.aligned.m16n8k8.row.col.f32.tf32.tf32.f32 "
        "{%0,%1,%2,%3}, {%4,%5,%6,%7}, {%8,%9}, {%0,%1,%2,%3};"
        : "+f"(c[0]), "+f"(c[1]), "+f"(c[2]), "+f"(c[3])
        : "r"(a[0]), "r"(a[1]), "r"(a[2]), "r"(a[3]), "r"(b[0]), "r"(b[1]));
}

// ---------------------------------------------------------------------------
// tf32 mma.sync NT GEMM: C[M,N] = A[M,K] * B[N,K]^T (row-major, K contiguous)
// CTA: 256 threads (8 warps), tile 128 x BN, BK=16 double-buffered.
// Warp grid WGM x WGN (WGM*WGN==8); warp tile (128/WGM) x (BN/WGN).
// ---------------------------------------------------------------------------
template<int BN, int WGM, int WGN>
__global__ __launch_bounds__(256)
void gemm_mma_kernel(const float* __restrict__ A, int lda,
                     const float* __restrict__ B, int ldb,
                     float* __restrict__ C, int ldc, int K) {
    constexpr int BM = 128, BK = 16, PADK = BK + 4;
    constexpr int WM = BM / WGM, WN = BN / WGN;
    constexpr int MT = WM / 16, NT = WN / 8;
    constexpr int AQ = (BM * BK / 4) / 256;     // float4 loads per thread for A (=2)
    constexpr int BQ = (BN * BK / 4) / 256;     // for B (2 if BN=128, 1 if BN=64)
    constexpr int BQn = (BQ > 0) ? BQ : 1;

    __shared__ float As[2][BM][PADK];
    __shared__ float Bs[2][BN][PADK];

    const int tid  = threadIdx.x;
    const int lane = tid & 31;
    const int warp = tid >> 5;
    const int m0 = blockIdx.x * BM;
    const int n0 = blockIdx.y * BN;
    const int wm = (warp % WGM) * WM;
    const int wn = (warp / WGM) * WN;
    const int gr = tid >> 2;            // load row (0..63)
    const int gc = (tid & 3) * 4;       // load col (0,4,8,12)
    const int qrow = lane >> 2;         // fragment row-in-group
    const int qk   = lane & 3;          // fragment k-in-group

    float4 areg[AQ], breg[BQn];

    auto ldg = [&](int k0) {
        #pragma unroll
        for (int q = 0; q < AQ; q++)
            areg[q] = *(const float4*)(A + (size_t)(m0 + gr + q * 64) * lda + k0 + gc);
        #pragma unroll
        for (int q = 0; q < BQn; q++)
            breg[q] = *(const float4*)(B + (size_t)(n0 + gr + q * 64) * ldb + k0 + gc);
    };
    auto sts = [&](int s) {
        #pragma unroll
        for (int q = 0; q < AQ; q++)
            *(float4*)&As[s][gr + q * 64][gc] = areg[q];
        #pragma unroll
        for (int q = 0; q < BQn; q++)
            *(float4*)&Bs[s][gr + q * 64][gc] = breg[q];
    };

    float acc[MT][NT][4];
    #pragma unroll
    for (int i = 0; i < MT; i++)
        #pragma unroll
        for (int j = 0; j < NT; j++)
            #pragma unroll
            for (int v = 0; v < 4; v++) acc[i][j][v] = 0.0f;

    const int NK = K / BK;
    ldg(0);
    sts(0);
    __syncthreads();

    for (int kt = 0; kt < NK; kt++) {
        const int s = kt & 1;
        const float (*Asl)[PADK] = As[s];
        const float (*Bsl)[PADK] = Bs[s];
        if (kt + 1 < NK) ldg((kt + 1) * BK);

        #pragma unroll
        for (int kk = 0; kk < BK; kk += 8) {
            uint32_t af[MT][4];
            #pragma unroll
            for (int mt = 0; mt < MT; mt++) {
                const int r = wm + mt * 16 + qrow;
                af[mt][0] = f2tf(Asl[r    ][kk + qk    ]);
                af[mt][1] = f2tf(Asl[r + 8][kk + qk    ]);
                af[mt][2] = f2tf(Asl[r    ][kk + qk + 4]);
                af[mt][3] = f2tf(Asl[r + 8][kk + qk + 4]);
            }
            uint32_t bf[NT][2];
            #pragma unroll
            for (int nt = 0; nt < NT; nt++) {
                const int c = wn + nt * 8 + qrow;
                bf[nt][0] = f2tf(Bsl[c][kk + qk    ]);
                bf[nt][1] = f2tf(Bsl[c][kk + qk + 4]);
            }
            #pragma unroll
            for (int mt = 0; mt < MT; mt++)
                #pragma unroll
                for (int nt = 0; nt < NT; nt++)
                    mma_tf32(acc[mt][nt], af[mt], bf[nt]);
        }

        if (kt + 1 < NK) sts((kt + 1) & 1);
        __syncthreads();
    }

    // epilogue: c0,c1 at (row, 2*qk), c2,c3 at (row+8, 2*qk)
    #pragma unroll
    for (int mt = 0; mt < MT; mt++) {
        const int r = m0 + wm + mt * 16 + qrow;
        #pragma unroll
        for (int nt = 0; nt < NT; nt++) {
            const int c = n0 + wn + nt * 8 + 2 * qk;
            float2 lo = make_float2(acc[mt][nt][0], acc[mt][nt][1]);
            float2 hi = make_float2(acc[mt][nt][2], acc[mt][nt][3]);
            *(float2*)(C + (size_t)r * ldc + c)       = lo;
            *(float2*)(C + (size_t)(r + 8) * ldc + c) = hi;
        }
    }
}

// ---------------------------------------------------------------------------
// K0: A = -exp(A_log)
// ---------------------------------------------------------------------------
__global__ void prep_A_kernel(const float* __restrict__ a_log, float* __restrict__ a_out, int n) {
    int i = blockIdx.x * blockDim.x + threadIdx.x;
    if (i < n) a_out[i] = -expf(a_log[i]);
}

// ---------------------------------------------------------------------------
// K1: rmsnorm
// ---------------------------------------------------------------------------
__global__ __launch_bounds__(256)
void rmsnorm_kernel(const float* __restrict__ x, const float* __restrict__ w,
                    float* __restrict__ o) {
    int tok = blockIdx.x;
    int tid = threadIdx.x;
    size_t base = (size_t)tok * DIMD;
    float4 v = *(const float4*)(x + base + tid * 4);
    float ss = v.x*v.x + v.y*v.y + v.z*v.z + v.w*v.w;
    #pragma unroll
    for (int off = 16; off > 0; off >>= 1)
        ss += __shfl_xor_sync(0xffffffffu, ss, off);
    __shared__ float red[8];
    if ((tid & 31) == 0) red[tid >> 5] = ss;
    __syncthreads();
    float tot = red[0] + red[1] + red[2] + red[3] + red[4] + red[5] + red[6] + red[7];
    float s = rsqrtf(tot * (1.0f / (float)DIMD) + 1e-6f);
    float4 wv = *(const float4*)(w + tid * 4);
    float4 r;
    r.x = v.x * s * wv.x; r.y = v.y * s * wv.y;
    r.z = v.z * s * wv.z; r.w = v.w * s * wv.w;
    *(float4*)(o + base + tid * 4) = r;
}

// ---------------------------------------------------------------------------
// K3 (SIMT): dt = softplus(proj[:, :64] @ dtw^T + dtb) — small K=64
// ---------------------------------------------------------------------------
__global__ __launch_bounds__(256)
void gemm_dt_kernel(const float* __restrict__ A, int lda,
                    const float* __restrict__ B, int ldb,
                    float* __restrict__ C, int ldc,
                    int K, const float* __restrict__ bias) {
    constexpr int BM = 128, BN = 64, BK = 16, TM = 8, TN = 4;
    __shared__ float As[BK][BM];
    __shared__ float Bs[BK][BN];

    int tid = threadIdx.x;
    int m0 = blockIdx.x * BM;
    int n0 = blockIdx.y * BN;
    int tx = tid & 15;
    int ty = tid >> 4;
    int row0 = ty * TM;
    int col0 = tx * TN;

    float acc[TM][TN];
    #pragma unroll
    for (int i = 0; i < TM; i++)
        #pragma unroll
        for (int j = 0; j < TN; j++) acc[i][j] = 0.0f;

    for (int k0 = 0; k0 < K; k0 += BK) {
        #pragma unroll
        for (int q = 0; q < 2; q++) {
            int i = tid + q * 256;
            int r = i >> 2, c4 = i & 3;
            float4 v = *(const float4*)(A + (size_t)(m0 + r) * lda + k0 + c4 * 4);
            As[c4 * 4 + 0][r] = v.x;
            As[c4 * 4 + 1][r] = v.y;
            As[c4 * 4 + 2][r] = v.z;
            As[c4 * 4 + 3][r] = v.w;
        }
        {
            int r = tid >> 2, c4 = tid & 3;
            float4 v = *(const float4*)(B + (size_t)(n0 + r) * ldb + k0 + c4 * 4);
            Bs[c4 * 4 + 0][r] = v.x;
            Bs[c4 * 4 + 1][r] = v.y;
            Bs[c4 * 4 + 2][r] = v.z;
            Bs[c4 * 4 + 3][r] = v.w;
        }
        __syncthreads();
        #pragma unroll
        for (int kk = 0; kk < BK; kk++) {
            float4 a0 = *(const float4*)&As[kk][row0];
            float4 a1 = *(const float4*)&As[kk][row0 + 4];
            float4 bv = *(const float4*)&Bs[kk][col0];
            float a[TM] = {a0.x, a0.y, a0.z, a0.w, a1.x, a1.y, a1.z, a1.w};
            float b[TN] = {bv.x, bv.y, bv.z, bv.w};
            #pragma unroll
            for (int i = 0; i < TM; i++)
                #pragma unroll
                for (int j = 0; j < TN; j++)
                    acc[i][j] = fmaf(a[i], b[j], acc[i][j]);
        }
        __syncthreads();
    }

    #pragma unroll
    for (int i = 0; i < TM; i++) {
        size_t off = (size_t)(m0 + row0 + i) * ldc + n0 + col0;
        float4 v;
        float t[TN];
        #pragma unroll
        for (int j = 0; j < TN; j++) {
            float a = acc[i][j] + bias[n0 + col0 + j];
            t[j] = fmaxf(a, 0.0f) + log1pf(__expf(-fabsf(a)));
        }
        v.x = t[0]; v.y = t[1]; v.z = t[2]; v.w = t[3];
        *(float4*)(C + off) = v;
    }
}

// ---------------------------------------------------------------------------
// K4: chunked selective scan
// ---------------------------------------------------------------------------
__global__ __launch_bounds__(128, 2)
void scan_kernel(const float* __restrict__ xn, const float* __restrict__ dt,
                 const float* __restrict__ proj, const float* __restrict__ Aarr,
                 const float* __restrict__ xorig, const float* __restrict__ Dvec,
                 float* __restrict__ yout) {
    __shared__ float4 BC[CHUNKT * 32];

    int chunk = blockIdx.x;
    int dbase = blockIdx.y * 128;
    int tid = threadIdx.x;
    int tok0 = chunk * CHUNKT;
    int d = dbase + tid;

    for (int i = tid; i < CHUNKT * 32; i += 128) {
        int t = i >> 5;
        int j = i & 31;
        BC[t * 32 + j] = *(const float4*)(proj + (size_t)(tok0 + t) * PDIM + DTRANK + j * 4);
    }

    float Areg[STATE];
    {
        const float4* Ar = (const float4*)(Aarr + (size_t)d * STATE);
        #pragma unroll
        for (int j = 0; j < 16; j++) {
            float4 v = Ar[j];
            Areg[4 * j + 0] = v.x; Areg[4 * j + 1] = v.y;
            Areg[4 * j + 2] = v.z; Areg[4 * j + 3] = v.w;
        }
    }
    float h[STATE];
    #pragma unroll
    for (int n = 0; n < STATE; n++) h[n] = 0.0f;

    float Dd = Dvec[d];
    __syncthreads();

    size_t base = (size_t)tok0 * DIMD + d;
    float dt_n = dt[base];
    float xn_n = xn[base];
    float xo_n = xorig[base];

    for (int t = 0; t < CHUNKT; t++) {
        float dtc = dt_n, xnc = xn_n, xoc = xo_n;
        if (t < CHUNKT - 1) {
            size_t b2 = base + (size_t)(t + 1) * DIMD;
            dt_n = dt[b2]; xn_n = xn[b2]; xo_n = xorig[b2];
        }
        float dx = dtc * xnc;
        float y = 0.0f;
        const float4* Bt = &BC[t * 32];
        #pragma unroll
        for (int j = 0; j < 16; j++) {
            float4 b4 = Bt[j];
            float4 c4 = Bt[j + 16];
            float e0 = __expf(dtc * Areg[4 * j + 0]);
            float e1 = __expf(dtc * Areg[4 * j + 1]);
            float e2 = __expf(dtc * Areg[4 * j + 2]);
            float e3 = __expf(dtc * Areg[4 * j + 3]);
            h[4 * j + 0] = fmaf(e0, h[4 * j + 0], dx * b4.x);
            h[4 * j + 1] = fmaf(e1, h[4 * j + 1], dx * b4.y);
            h[4 * j + 2] = fmaf(e2, h[4 * j + 2], dx * b4.z);
            h[4 * j + 3] = fmaf(e3, h[4 * j + 3], dx * b4.w);
            y = fmaf(h[4 * j + 0], c4.x, y);
            y = fmaf(h[4 * j + 1], c4.y, y);
            y = fmaf(h[4 * j + 2], c4.z, y);
            y = fmaf(h[4 * j + 3], c4.w, y);
        }
        yout[base + (size_t)t * DIMD] = y + xoc * Dd;
    }
}

// ---------------------------------------------------------------------------
// launch
// ---------------------------------------------------------------------------
extern "C" void kernel_launch(void* const* d_in, const int* in_sizes, int n_in,
                              void* d_out, int out_size) {
    const float* x      = (const float*)d_in[0];
    const float* norm_w = (const float*)d_in[1];
    const float* xpw    = (const float*)d_in[2];   // [192,1024]
    const float* dtw    = (const float*)d_in[3];   // [1024,64]
    const float* dtb    = (const float*)d_in[4];
    const float* alog   = (const float*)d_in[5];
    const float* Dvec   = (const float*)d_in[6];
    const float* ow     = (const float*)d_in[7];   // [1024,1024]
    float* out = (float*)d_out;

    int tokens = in_sizes[0] / DIMD;               // 8192

    float *p_xn, *p_proj, *p_dt, *p_y, *p_A;
    cudaGetSymbolAddress((void**)&p_xn,   g_xn);
    cudaGetSymbolAddress((void**)&p_proj, g_proj);
    cudaGetSymbolAddress((void**)&p_dt,   g_dt);
    cudaGetSymbolAddress((void**)&p_y,    g_y);
    cudaGetSymbolAddress((void**)&p_A,    g_A);

    // K0: A = -exp(A_log)
    prep_A_kernel<<<(DIMD * STATE + 255) / 256, 256>>>(alog, p_A, DIMD * STATE);

    // K1: rmsnorm
    rmsnorm_kernel<<<tokens, 256>>>(x, norm_w, p_xn);

    // K2: proj = xn @ xpw^T   [tokens,192]  (tf32 mma, BN=64)
    gemm_mma_kernel<64, 4, 2><<<dim3(tokens / 128, PDIM / 64), 256>>>(
        p_xn, DIMD, xpw, DIMD, p_proj, PDIM, DIMD);

    // K3: dt = softplus(proj[:, :64] @ dtw^T + dtb)
    gemm_dt_kernel<<<dim3(tokens / 128, DIMD / 64), 256>>>(
        p_proj, PDIM, dtw, DTRANK, p_dt, DIMD, DTRANK, dtb);

    // K4: scan -> y + x*D
    scan_kernel<<<dim3(tokens / CHUNKT, DIMD / 128), 128>>>(
        p_xn, p_dt, p_proj, p_A, x, Dvec, p_y);

    // K5: out = y @ ow^T   [tokens,1024]  (tf32 mma, BN=128)
    gemm_mma_kernel<128, 2, 4><<<dim3(tokens / 128, DIMD / 128), 256>>>(
        p_y, DIMD, ow, DIMD, out, DIMD, DIMD);
}

// round 6
// speedup vs baseline: 1.6658x; 1.0297x over previous
#include <cuda_runtime.h>
#include <cuda_bf16.h>
#include <math.h>
#include <stdint.h>

// ---------------------------------------------------------------------------
// ParallelSSM: rmsnorm -> proj -> (softplus dt) -> chunked selective scan -> out proj
// tokens = B*L = 8192, DIM=1024, STATE=64, DT_RANK=64, CHUNK=64, P=192
// K=1024 GEMMs via mma.sync tf32 with fragment-major SMEM (convert at STS).
// ---------------------------------------------------------------------------

#define DIMD   1024
#define STATE  64
#define DTRANK 64
#define CHUNKT 64
#define PDIM   192
#define MAX_TOKENS 8192

// Scratch (device globals: allocation-free rule)
__device__ float g_xn  [(size_t)MAX_TOKENS * DIMD];
__device__ float g_proj[(size_t)MAX_TOKENS * PDIM];
__device__ float g_dt  [(size_t)MAX_TOKENS * DIMD];
__device__ float g_y   [(size_t)MAX_TOKENS * DIMD];
__device__ float g_A   [(size_t)DIMD * STATE];

// ============================ mma.sync helpers =============================
__device__ __forceinline__ uint32_t f2tf(float x) {
    uint32_t u;
    asm("cvt.rna.tf32.f32 %0, %1;" : "=r"(u) : "f"(x));
    return u;
}

__device__ __forceinline__ void mma_tf32(float c[4], const uint32_t a[4], const uint32_t b[2]) {
    asm volatile(
        "mma.sync.aligned.m16n8k8.row.col.f32.tf32.tf32.f32 "
        "{%0,%1,%2,%3}, {%4,%5,%6,%7}, {%8,%9}, {%0,%1,%2,%3};"
        : "+f"(c[0]), "+f"(c[1]), "+f"(c[2]), "+f"(c[3])
        : "r"(a[0]), "r"(a[1]), "r"(a[2]), "r"(a[3]), "r"(b[0]), "r"(b[1]));
}

// ---------------------------------------------------------------------------
// tf32 mma.sync NT GEMM, fragment-major SMEM:
//   C[M,N] = A[M,K] * B[N,K]^T (row-major, K contiguous)
// CTA: 256 threads (8 warps), tile 128 x BN, BK=16 double-buffered.
// SMEM holds tf32 bits arranged so each lane's MMA fragment is contiguous:
//   A: [stage][mg(8)][kg(2)][lane(32)][4]  (lane frag = a0,a1,a2,a3; 16B LDS)
//   B: [stage][ng(BN/8)][kg(2)][lane(32)][2] (lane frag = b0,b1; 8B LDS)
// Fragment map (m16n8k8, qrow=lane>>2, qk=lane&3):
//   a0=(qrow,qk) a1=(qrow+8,qk) a2=(qrow,qk+4) a3=(qrow+8,qk+4)
//   b0=(n=qrow,k=qk) b1=(n=qrow,k=qk+4)
// ---------------------------------------------------------------------------
template<int BN, int WGM, int WGN>
__global__ __launch_bounds__(256)
void gemm_mma_kernel(const float* __restrict__ A, int lda,
                     const float* __restrict__ B, int ldb,
                     float* __restrict__ C, int ldc, int K) {
    constexpr int BM = 128, BK = 16;
    constexpr int WM = BM / WGM, WN = BN / WGN;
    constexpr int MT = WM / 16, NT = WN / 8;
    constexpr int AQ = 2;                        // A rows per thread (gr, gr+64)
    constexpr int BQ = (BN * BK / 4) / 256;      // 2 if BN=128, 1 if BN=64
    constexpr int BQn = (BQ > 0) ? BQ : 1;
    constexpr int NG = BN / 8;

    __shared__ __align__(16) uint32_t Asf[2][8][2][32][4];
    __shared__ __align__(16) uint32_t Bsf[2][NG][2][32][2];

    const int tid  = threadIdx.x;
    const int lane = tid & 31;
    const int warp = tid >> 5;
    const int m0 = blockIdx.x * BM;
    const int n0 = blockIdx.y * BN;
    const int wm16 = (warp % WGM) * MT;          // A mgroup base
    const int wn8  = (warp / WGM) * NT;          // B ngroup base
    const int gr = tid >> 2;                     // load row (0..63)
    const int gc = (tid & 3) * 4;                // load col (0,4,8,12)
    const int qrow = lane >> 2;
    const int qk   = lane & 3;

    // per-thread store decomposition (k = gc+i, i=0..3):
    const int kg_st   = gc >> 3;                 // k group
    const int khalf   = (gc & 7) >> 2;           // 0: a0/a1 slots, 1: a2/a3 slots

    float4 areg[AQ], breg[BQn];

    auto ldg = [&](int k0) {
        #pragma unroll
        for (int q = 0; q < AQ; q++)
            areg[q] = *(const float4*)(A + (size_t)(m0 + gr + q * 64) * lda + k0 + gc);
        #pragma unroll
        for (int q = 0; q < BQn; q++)
            breg[q] = *(const float4*)(B + (size_t)(n0 + gr + q * 64) * ldb + k0 + gc);
    };
    auto sts = [&](int s) {
        #pragma unroll
        for (int q = 0; q < AQ; q++) {
            const int r = gr + q * 64;
            const int mg = r >> 4, rr = r & 15;
            const int qr = rr & 7, half = rr >> 3;
            const int aidx = half + 2 * khalf;
            uint32_t* dst = &Asf[s][mg][kg_st][qr * 4][aidx];   // +16B per qk
            float4 v = areg[q];
            dst[0 * 4] = f2tf(v.x);
            dst[1 * 4] = f2tf(v.y);
            dst[2 * 4] = f2tf(v.z);
            dst[3 * 4] = f2tf(v.w);
        }
        #pragma unroll
        for (int q = 0; q < BQn; q++) {
            const int n = gr + q * 64;
            const int ng = n >> 3, qr = n & 7;
            uint32_t* dst = &Bsf[s][ng][kg_st][qr * 4][khalf];  // +8B per qk
            float4 v = breg[q];
            dst[0 * 2] = f2tf(v.x);
            dst[1 * 2] = f2tf(v.y);
            dst[2 * 2] = f2tf(v.z);
            dst[3 * 2] = f2tf(v.w);
        }
    };

    float acc[MT][NT][4];
    #pragma unroll
    for (int i = 0; i < MT; i++)
        #pragma unroll
        for (int j = 0; j < NT; j++)
            #pragma unroll
            for (int v = 0; v < 4; v++) acc[i][j][v] = 0.0f;

    const int NK = K / BK;
    ldg(0);
    sts(0);
    __syncthreads();

    for (int kt = 0; kt < NK; kt++) {
        const int s = kt & 1;
        if (kt + 1 < NK) ldg((kt + 1) * BK);

        #pragma unroll
        for (int kg = 0; kg < 2; kg++) {
            uint32_t af[MT][4];
            uint32_t bf[NT][2];
            #pragma unroll
            for (int mt = 0; mt < MT; mt++)
                *(uint4*)af[mt] = *(const uint4*)&Asf[s][wm16 + mt][kg][lane][0];
            #pragma unroll
            for (int nt = 0; nt < NT; nt++)
                *(uint2*)bf[nt] = *(const uint2*)&Bsf[s][wn8 + nt][kg][lane][0];
            #pragma unroll
            for (int mt = 0; mt < MT; mt++)
                #pragma unroll
                for (int nt = 0; nt < NT; nt++)
                    mma_tf32(acc[mt][nt], af[mt], bf[nt]);
        }

        if (kt + 1 < NK) sts((kt + 1) & 1);
        __syncthreads();
    }

    // epilogue: c0,c1 at (row, 2*qk), c2,c3 at (row+8, 2*qk)
    #pragma unroll
    for (int mt = 0; mt < MT; mt++) {
        const int r = m0 + (wm16 + mt) * 16 + qrow;
        #pragma unroll
        for (int nt = 0; nt < NT; nt++) {
            const int c = n0 + (wn8 + nt) * 8 + 2 * qk;
            float2 lo = make_float2(acc[mt][nt][0], acc[mt][nt][1]);
            float2 hi = make_float2(acc[mt][nt][2], acc[mt][nt][3]);
            *(float2*)(C + (size_t)r * ldc + c)       = lo;
            *(float2*)(C + (size_t)(r + 8) * ldc + c) = hi;
        }
    }
}

// ---------------------------------------------------------------------------
// K0: A = -exp(A_log)
// ---------------------------------------------------------------------------
__global__ void prep_A_kernel(const float* __restrict__ a_log, float* __restrict__ a_out, int n) {
    int i = blockIdx.x * blockDim.x + threadIdx.x;
    if (i < n) a_out[i] = -expf(a_log[i]);
}

// ---------------------------------------------------------------------------
// K1: rmsnorm
// ---------------------------------------------------------------------------
__global__ __launch_bounds__(256)
void rmsnorm_kernel(const float* __restrict__ x, const float* __restrict__ w,
                    float* __restrict__ o) {
    int tok = blockIdx.x;
    int tid = threadIdx.x;
    size_t base = (size_t)tok * DIMD;
    float4 v = *(const float4*)(x + base + tid * 4);
    float ss = v.x*v.x + v.y*v.y + v.z*v.z + v.w*v.w;
    #pragma unroll
    for (int off = 16; off > 0; off >>= 1)
        ss += __shfl_xor_sync(0xffffffffu, ss, off);
    __shared__ float red[8];
    if ((tid & 31) == 0) red[tid >> 5] = ss;
    __syncthreads();
    float tot = red[0] + red[1] + red[2] + red[3] + red[4] + red[5] + red[6] + red[7];
    float s = rsqrtf(tot * (1.0f / (float)DIMD) + 1e-6f);
    float4 wv = *(const float4*)(w + tid * 4);
    float4 r;
    r.x = v.x * s * wv.x; r.y = v.y * s * wv.y;
    r.z = v.z * s * wv.z; r.w = v.w * s * wv.w;
    *(float4*)(o + base + tid * 4) = r;
}

// ---------------------------------------------------------------------------
// K3 (SIMT): dt = softplus(proj[:, :64] @ dtw^T + dtb) — small K=64
// ---------------------------------------------------------------------------
__global__ __launch_bounds__(256)
void gemm_dt_kernel(const float* __restrict__ A, int lda,
                    const float* __restrict__ B, int ldb,
                    float* __restrict__ C, int ldc,
                    int K, const float* __restrict__ bias) {
    constexpr int BM = 128, BN = 64, BK = 16, TM = 8, TN = 4;
    __shared__ float As[BK][BM];
    __shared__ float Bs[BK][BN];

    int tid = threadIdx.x;
    int m0 = blockIdx.x * BM;
    int n0 = blockIdx.y * BN;
    int tx = tid & 15;
    int ty = tid >> 4;
    int row0 = ty * TM;
    int col0 = tx * TN;

    float acc[TM][TN];
    #pragma unroll
    for (int i = 0; i < TM; i++)
        #pragma unroll
        for (int j = 0; j < TN; j++) acc[i][j] = 0.0f;

    for (int k0 = 0; k0 < K; k0 += BK) {
        #pragma unroll
        for (int q = 0; q < 2; q++) {
            int i = tid + q * 256;
            int r = i >> 2, c4 = i & 3;
            float4 v = *(const float4*)(A + (size_t)(m0 + r) * lda + k0 + c4 * 4);
            As[c4 * 4 + 0][r] = v.x;
            As[c4 * 4 + 1][r] = v.y;
            As[c4 * 4 + 2][r] = v.z;
            As[c4 * 4 + 3][r] = v.w;
        }
        {
            int r = tid >> 2, c4 = tid & 3;
            float4 v = *(const float4*)(B + (size_t)(n0 + r) * ldb + k0 + c4 * 4);
            Bs[c4 * 4 + 0][r] = v.x;
            Bs[c4 * 4 + 1][r] = v.y;
            Bs[c4 * 4 + 2][r] = v.z;
            Bs[c4 * 4 + 3][r] = v.w;
        }
        __syncthreads();
        #pragma unroll
        for (int kk = 0; kk < BK; kk++) {
            float4 a0 = *(const float4*)&As[kk][row0];
            float4 a1 = *(const float4*)&As[kk][row0 + 4];
            float4 bv = *(const float4*)&Bs[kk][col0];
            float a[TM] = {a0.x, a0.y, a0.z, a0.w, a1.x, a1.y, a1.z, a1.w};
            float b[TN] = {bv.x, bv.y, bv.z, bv.w};
            #pragma unroll
            for (int i = 0; i < TM; i++)
                #pragma unroll
                for (int j = 0; j < TN; j++)
                    acc[i][j] = fmaf(a[i], b[j], acc[i][j]);
        }
        __syncthreads();
    }

    #pragma unroll
    for (int i = 0; i < TM; i++) {
        size_t off = (size_t)(m0 + row0 + i) * ldc + n0 + col0;
        float4 v;
        float t[TN];
        #pragma unroll
        for (int j = 0; j < TN; j++) {
            float a = acc[i][j] + bias[n0 + col0 + j];
            t[j] = fmaxf(a, 0.0f) + log1pf(__expf(-fabsf(a)));
        }
        v.x = t[0]; v.y = t[1]; v.z = t[2]; v.w = t[3];
        *(float4*)(C + off) = v;
    }
}

// ---------------------------------------------------------------------------
// K4: chunked selective scan. Runtime uniform-A fast path: when all 64 A
// values of this d-row are identical (exact register compare), the 64
// exponentials per (t,d) collapse to one — mathematically identical result.
// ---------------------------------------------------------------------------
__global__ __launch_bounds__(128, 2)
void scan_kernel(const float* __restrict__ xn, const float* __restrict__ dt,
                 const float* __restrict__ proj, const float* __restrict__ Aarr,
                 const float* __restrict__ xorig, const float* __restrict__ Dvec,
                 float* __restrict__ yout) {
    __shared__ float4 BC[CHUNKT * 32];

    int chunk = blockIdx.x;
    int dbase = blockIdx.y * 128;
    int tid = threadIdx.x;
    int tok0 = chunk * CHUNKT;
    int d = dbase + tid;

    for (int i = tid; i < CHUNKT * 32; i += 128) {
        int t = i >> 5;
        int j = i & 31;
        BC[t * 32 + j] = *(const float4*)(proj + (size_t)(tok0 + t) * PDIM + DTRANK + j * 4);
    }

    float Areg[STATE];
    {
        const float4* Ar = (const float4*)(Aarr + (size_t)d * STATE);
        #pragma unroll
        for (int j = 0; j < 16; j++) {
            float4 v = Ar[j];
            Areg[4 * j + 0] = v.x; Areg[4 * j + 1] = v.y;
            Areg[4 * j + 2] = v.z; Areg[4 * j + 3] = v.w;
        }
    }
    bool uniformA = true;
    #pragma unroll
    for (int n = 1; n < STATE; n++) uniformA &= (Areg[n] == Areg[0]);
    const float a0 = Areg[0];

    float h[STATE];
    #pragma unroll
    for (int n = 0; n < STATE; n++) h[n] = 0.0f;

    float Dd = Dvec[d];
    __syncthreads();

    size_t base = (size_t)tok0 * DIMD + d;
    float dt_n = dt[base];
    float xn_n = xn[base];
    float xo_n = xorig[base];

    if (uniformA) {
        for (int t = 0; t < CHUNKT; t++) {
            float dtc = dt_n, xnc = xn_n, xoc = xo_n;
            if (t < CHUNKT - 1) {
                size_t b2 = base + (size_t)(t + 1) * DIMD;
                dt_n = dt[b2]; xn_n = xn[b2]; xo_n = xorig[b2];
            }
            float dx = dtc * xnc;
            float e = __expf(dtc * a0);
            float y = 0.0f;
            const float4* Bt = &BC[t * 32];
            #pragma unroll
            for (int j = 0; j < 16; j++) {
                float4 b4 = Bt[j];
                float4 c4 = Bt[j + 16];
                h[4 * j + 0] = fmaf(e, h[4 * j + 0], dx * b4.x);
                h[4 * j + 1] = fmaf(e, h[4 * j + 1], dx * b4.y);
                h[4 * j + 2] = fmaf(e, h[4 * j + 2], dx * b4.z);
                h[4 * j + 3] = fmaf(e, h[4 * j + 3], dx * b4.w);
                y = fmaf(h[4 * j + 0], c4.x, y);
                y = fmaf(h[4 * j + 1], c4.y, y);
                y = fmaf(h[4 * j + 2], c4.z, y);
                y = fmaf(h[4 * j + 3], c4.w, y);
            }
            yout[base + (size_t)t * DIMD] = y + xoc * Dd;
        }
    } else {
        for (int t = 0; t < CHUNKT; t++) {
            float dtc = dt_n, xnc = xn_n, xoc = xo_n;
            if (t < CHUNKT - 1) {
                size_t b2 = base + (size_t)(t + 1) * DIMD;
                dt_n = dt[b2]; xn_n = xn[b2]; xo_n = xorig[b2];
            }
            float dx = dtc * xnc;
            float y = 0.0f;
            const float4* Bt = &BC[t * 32];
            #pragma unroll
            for (int j = 0; j < 16; j++) {
                float4 b4 = Bt[j];
                float4 c4 = Bt[j + 16];
                float e0 = __expf(dtc * Areg[4 * j + 0]);
                float e1 = __expf(dtc * Areg[4 * j + 1]);
                float e2 = __expf(dtc * Areg[4 * j + 2]);
                float e3 = __expf(dtc * Areg[4 * j + 3]);
                h[4 * j + 0] = fmaf(e0, h[4 * j + 0], dx * b4.x);
                h[4 * j + 1] = fmaf(e1, h[4 * j + 1], dx * b4.y);
                h[4 * j + 2] = fmaf(e2, h[4 * j + 2], dx * b4.z);
                h[4 * j + 3] = fmaf(e3, h[4 * j + 3], dx * b4.w);
                y = fmaf(h[4 * j + 0], c4.x, y);
                y = fmaf(h[4 * j + 1], c4.y, y);
                y = fmaf(h[4 * j + 2], c4.z, y);
                y = fmaf(h[4 * j + 3], c4.w, y);
            }
            yout[base + (size_t)t * DIMD] = y + xoc * Dd;
        }
    }
}

// ---------------------------------------------------------------------------
// launch
// ---------------------------------------------------------------------------
extern "C" void kernel_launch(void* const* d_in, const int* in_sizes, int n_in,
                              void* d_out, int out_size) {
    const float* x      = (const float*)d_in[0];
    const float* norm_w = (const float*)d_in[1];
    const float* xpw    = (const float*)d_in[2];   // [192,1024]
    const float* dtw    = (const float*)d_in[3];   // [1024,64]
    const float* dtb    = (const float*)d_in[4];
    const float* alog   = (const float*)d_in[5];
    const float* Dvec   = (const float*)d_in[6];
    const float* ow     = (const float*)d_in[7];   // [1024,1024]
    float* out = (float*)d_out;

    int tokens = in_sizes[0] / DIMD;               // 8192

    float *p_xn, *p_proj, *p_dt, *p_y, *p_A;
    cudaGetSymbolAddress((void**)&p_xn,   g_xn);
    cudaGetSymbolAddress((void**)&p_proj, g_proj);
    cudaGetSymbolAddress((void**)&p_dt,   g_dt);
    cudaGetSymbolAddress((void**)&p_y,    g_y);
    cudaGetSymbolAddress((void**)&p_A,    g_A);

    // K0: A = -exp(A_log)
    prep_A_kernel<<<(DIMD * STATE + 255) / 256, 256>>>(alog, p_A, DIMD * STATE);

    // K1: rmsnorm
    rmsnorm_kernel<<<tokens, 256>>>(x, norm_w, p_xn);

    // K2: proj = xn @ xpw^T   [tokens,192]  (tf32 mma, BN=64)
    gemm_mma_kernel<64, 4, 2><<<dim3(tokens / 128, PDIM / 64), 256>>>(
        p_xn, DIMD, xpw, DIMD, p_proj, PDIM, DIMD);

    // K3: dt = softplus(proj[:, :64] @ dtw^T + dtb)
    gemm_dt_kernel<<<dim3(tokens / 128, DIMD / 64), 256>>>(
        p_proj, PDIM, dtw, DTRANK, p_dt, DIMD, DTRANK, dtb);

    // K4: scan -> y + x*D
    scan_kernel<<<dim3(tokens / CHUNKT, DIMD / 128), 128>>>(
        p_xn, p_dt, p_proj, p_A, x, Dvec, p_y);

    // K5: out = y @ ow^T   [tokens,1024]  (tf32 mma, BN=128)
    gemm_mma_kernel<128, 2, 4><<<dim3(tokens / 128, DIMD / 128), 256>>>(
        p_y, DIMD, ow, DIMD, out, DIMD, DIMD);
}